// round 3
// baseline (speedup 1.0000x reference)
#include <cuda_runtime.h>
#include <cuda_bf16.h>
#include <cstdint>

// Problem constants
#define N_ANCH   8192
#define DIM      64
#define NSPLIT   8
#define ITILE    256
#define NITILES  (N_ANCH / ITILE)          // 32
#define JRANGE   (N_ANCH / NSPLIT)         // 1024
#define TJ       128
#define MARGIN_F 0.5f
#define RBLOCKS  (N_ANCH / 256)            // 32

// Device scratch
__device__ float g_sq[N_ANCH];
__device__ float g_maxval[NSPLIT * N_ANCH];
__device__ int   g_maxidx[NSPLIT * N_ANCH];
__device__ float g_minval[NSPLIT * N_ANCH];
__device__ int   g_minidx[NSPLIT * N_ANCH];
__device__ float g_partial[RBLOCKS];

// Packed fp32x2 ops (sm_103a)
#define FMA2(d, a, b, c) \
    asm("fma.rn.f32x2 %0, %1, %2, %3;" : "=l"(d) : "l"(a), "l"(b), "l"(c))
#define ADD2(d, a, b) \
    asm("add.rn.f32x2 %0, %1, %2;" : "=l"(d) : "l"(a), "l"(b))
#define UNPACK2(lo, hi, v) \
    asm("mov.b64 {%0, %1}, %2;" : "=f"(lo), "=f"(hi) : "l"(v))

struct __align__(8) Meta { float sq; int tgt; };

// ---------------------------------------------------------------------------
// Kernel 0: per-row squared norms
// ---------------------------------------------------------------------------
__global__ void sqnorm_kernel(const float* __restrict__ emb) {
    int i = blockIdx.x * blockDim.x + threadIdx.x;
    if (i >= N_ANCH) return;
    const float4* r = reinterpret_cast<const float4*>(emb + (size_t)i * DIM);
    float s = 0.f;
#pragma unroll
    for (int k = 0; k < DIM / 4; k++) {
        float4 v = r[k];
        s += v.x * v.x + v.y * v.y + v.z * v.z + v.w * v.w;
    }
    g_sq[i] = s;
}

// ---------------------------------------------------------------------------
// Kernel 1: batch-hard mining, branch-free inner loop.
// Selection metric: key_j = sq_j - 2*dot(i,j)  (monotone in dist for fixed i).
// ---------------------------------------------------------------------------
__global__ __launch_bounds__(ITILE, 2)
void mine_kernel(const float* __restrict__ emb,
                 const int* __restrict__ tgt) {
    __shared__ float4 s_emb4[TJ * (DIM / 4)];   // 32 KB
    __shared__ Meta   s_meta[TJ];               // {sq, tgt} packed -> 1 LDS.64

    const int i = blockIdx.x * ITILE + threadIdx.x;
    const int split = blockIdx.y;

    // Anchor row in registers as 32 packed fp32 pairs.
    unsigned long long a[DIM / 2];
    {
        const ulonglong2* ar =
            reinterpret_cast<const ulonglong2*>(emb + (size_t)i * DIM);
#pragma unroll
        for (int k = 0; k < DIM / 4; k++) {
            ulonglong2 v = ar[k];
            a[2 * k]     = v.x;
            a[2 * k + 1] = v.y;
        }
    }
    const int mytgt = tgt[i];

    const float INF_F = __int_as_float(0x7f800000);
    float maxv = -INF_F; int maxj = 0;
    float minv =  INF_F; int minj = 0;

    const int j0 = split * JRANGE;
    for (int jc = 0; jc < JRANGE; jc += TJ) {
        const int jbase = j0 + jc;
        __syncthreads();
        {
            const float4* src =
                reinterpret_cast<const float4*>(emb + (size_t)jbase * DIM);
            for (int k = threadIdx.x; k < TJ * (DIM / 4); k += ITILE)
                s_emb4[k] = src[k];
            if (threadIdx.x < TJ) {
                Meta m;
                m.sq  = g_sq[jbase + threadIdx.x];
                m.tgt = tgt[jbase + threadIdx.x];
                s_meta[threadIdx.x] = m;
            }
        }
        __syncthreads();

#pragma unroll 2
        for (int jj = 0; jj < TJ; jj++) {
            const ulonglong2* b = reinterpret_cast<const ulonglong2*>(
                s_emb4 + jj * (DIM / 4));
            unsigned long long acc0 = 0ull, acc1 = 0ull,
                               acc2 = 0ull, acc3 = 0ull;
#pragma unroll
            for (int k = 0; k < DIM / 4; k += 2) {
                ulonglong2 b0 = b[k];
                ulonglong2 b1 = b[k + 1];
                FMA2(acc0, a[2 * k],     b0.x, acc0);
                FMA2(acc1, a[2 * k + 1], b0.y, acc1);
                FMA2(acc2, a[2 * k + 2], b1.x, acc2);
                FMA2(acc3, a[2 * k + 3], b1.y, acc3);
            }
            // Packed reduction: 8 lanes -> 1 scalar
            unsigned long long s01, s23, sAll;
            ADD2(s01, acc0, acc1);
            ADD2(s23, acc2, acc3);
            ADD2(sAll, s01, s23);
            float lo, hi;
            UNPACK2(lo, hi, sAll);
            float dot = lo + hi;

            Meta m = s_meta[jj];
            float key = fmaf(-2.0f, dot, m.sq);   // sq_j - 2*dot
            int   j   = jbase + jj;

            bool same = (m.tgt == mytgt);
            float kpos = same ? key : -INF_F;
            float kneg = same ? INF_F : key;

            bool c1 = kpos > maxv;                // strict: first occurrence
            maxv = c1 ? kpos : maxv;
            maxj = c1 ? j    : maxj;
            bool c2 = kneg < minv;
            minv = c2 ? kneg : minv;
            minj = c2 ? j    : minj;
        }
    }

    const int o = split * N_ANCH + i;
    g_maxval[o] = maxv; g_maxidx[o] = maxj;
    g_minval[o] = minv; g_minidx[o] = minj;
}

// ---------------------------------------------------------------------------
// Kernel 2: combine splits (ascending, strict) + exact ap/an + loss + reduce
// ---------------------------------------------------------------------------
__global__ void loss_kernel(const float* __restrict__ emb) {
    __shared__ float red[256];
    const int i = blockIdx.x * 256 + threadIdx.x;

    const float INF_F = __int_as_float(0x7f800000);
    float maxv = -INF_F; int p = 0;
    float minv =  INF_F; int n = 0;
#pragma unroll
    for (int s = 0; s < NSPLIT; s++) {
        const int o = s * N_ANCH + i;
        float v = g_maxval[o];
        if (v > maxv) { maxv = v; p = g_maxidx[o]; }
        v = g_minval[o];
        if (v < minv) { minv = v; n = g_minidx[o]; }
    }

    const float4* ei = reinterpret_cast<const float4*>(emb + (size_t)i * DIM);
    const float4* ep = reinterpret_cast<const float4*>(emb + (size_t)p * DIM);
    const float4* en = reinterpret_cast<const float4*>(emb + (size_t)n * DIM);
    float ap = 0.f, an = 0.f;
#pragma unroll
    for (int k = 0; k < DIM / 4; k++) {
        float4 vi = ei[k], vp = ep[k], vn = en[k];
        float dx;
        dx = vi.x - vp.x; ap += dx * dx;
        dx = vi.y - vp.y; ap += dx * dx;
        dx = vi.z - vp.z; ap += dx * dx;
        dx = vi.w - vp.w; ap += dx * dx;
        dx = vi.x - vn.x; an += dx * dx;
        dx = vi.y - vn.y; an += dx * dx;
        dx = vi.z - vn.z; an += dx * dx;
        dx = vi.w - vn.w; an += dx * dx;
    }
    float loss = fmaxf(ap - an + MARGIN_F, 0.0f);

    red[threadIdx.x] = loss;
    __syncthreads();
#pragma unroll
    for (int off = 128; off > 0; off >>= 1) {
        if (threadIdx.x < off) red[threadIdx.x] += red[threadIdx.x + off];
        __syncthreads();
    }
    if (threadIdx.x == 0) g_partial[blockIdx.x] = red[0];
}

// ---------------------------------------------------------------------------
// Kernel 3: final mean
// ---------------------------------------------------------------------------
__global__ void final_kernel(float* __restrict__ out) {
    if (threadIdx.x == 0) {
        float s = 0.f;
#pragma unroll
        for (int k = 0; k < RBLOCKS; k++) s += g_partial[k];
        out[0] = s / (float)N_ANCH;
    }
}

// ---------------------------------------------------------------------------
extern "C" void kernel_launch(void* const* d_in, const int* in_sizes, int n_in,
                              void* d_out, int out_size) {
    const float* emb = (const float*)d_in[0];
    const int*   tgt = (const int*)d_in[1];
    float*       out = (float*)d_out;

    sqnorm_kernel<<<N_ANCH / 256, 256>>>(emb);
    dim3 grid(NITILES, NSPLIT);
    mine_kernel<<<grid, ITILE>>>(emb, tgt);
    loss_kernel<<<RBLOCKS, 256>>>(emb);
    final_kernel<<<1, 32>>>(out);
}

// round 5
// speedup vs baseline: 2.4160x; 2.4160x over previous
#include <cuda_runtime.h>
#include <cuda_bf16.h>
#include <cstdint>

// ---------------------------------------------------------------- constants
#define N_ANCH   8192
#define DIM      64
#define JSPLIT   2
#define STRIPS   64            // 8192 / 128
#define BM       128
#define BN       128
#define CHUNKS   32            // 4096 / 128 per split
#define KSTEPS   12            // K = 192 = [hi|lo|hi]
#define THREADS  256
#define ROWB     400           // bytes per tile row: 192*2 + 16 pad (conflict-free)
#define MARGIN_F 0.5f
#define RBLOCKS  32

// SMEM layout
#define OFF_A    0
#define OFF_B0   51200
#define OFF_B1   102400
#define SMEM_TOTAL 153600      // 150 KB

struct __align__(8) Meta { float sq; int tgt; };

// ---------------------------------------------------------------- scratch
__device__ unsigned int g_ebf[N_ANCH * 64];   // per row: 32 u32 hi | 32 u32 lo
__device__ Meta  g_meta[N_ANCH];
__device__ float g_maxval[JSPLIT * N_ANCH];
__device__ int   g_maxidx[JSPLIT * N_ANCH];
__device__ float g_minval[JSPLIT * N_ANCH];
__device__ int   g_minidx[JSPLIT * N_ANCH];
__device__ float g_partial[RBLOCKS];

// ---------------------------------------------------------------- PTX helpers
__device__ __forceinline__ uint32_t smem_u32(const void* p) {
    uint32_t a;
    asm("{ .reg .u64 t; cvta.to.shared.u64 t, %1; cvt.u32.u64 %0, t; }"
        : "=r"(a) : "l"(p));
    return a;
}
#define CP16(d, s) \
    asm volatile("cp.async.cg.shared.global [%0], [%1], 16;" \
                 :: "r"(d), "l"(s) : "memory")
#define CP_COMMIT() asm volatile("cp.async.commit_group;" ::: "memory")
#define CP_WAIT1()  asm volatile("cp.async.wait_group 1;" ::: "memory")

#define LDSM_X4(R, addr) \
    asm volatile("ldmatrix.sync.aligned.m8n8.x4.shared.b16 {%0,%1,%2,%3}, [%4];" \
                 : "=r"((R)[0]), "=r"((R)[1]), "=r"((R)[2]), "=r"((R)[3]) \
                 : "r"(addr))

#define MMA16816(D, A, B0, B1) \
    asm volatile("mma.sync.aligned.m16n8k16.row.col.f32.bf16.bf16.f32 " \
                 "{%0,%1,%2,%3},{%4,%5,%6,%7},{%8,%9},{%0,%1,%2,%3};" \
                 : "+f"((D)[0]), "+f"((D)[1]), "+f"((D)[2]), "+f"((D)[3]) \
                 : "r"((A)[0]), "r"((A)[1]), "r"((A)[2]), "r"((A)[3]), \
                   "r"(B0), "r"(B1))

// ---------------------------------------------------------------- kernel 0a: norms+meta
__global__ void sqnorm_kernel(const float* __restrict__ emb,
                              const int* __restrict__ tgt) {
    int i = blockIdx.x * blockDim.x + threadIdx.x;
    if (i >= N_ANCH) return;
    const float4* r = reinterpret_cast<const float4*>(emb + (size_t)i * DIM);
    float s = 0.f;
#pragma unroll
    for (int k = 0; k < DIM / 4; k++) {
        float4 v = r[k];
        s += v.x * v.x + v.y * v.y + v.z * v.z + v.w * v.w;
    }
    Meta m; m.sq = s; m.tgt = tgt[i];
    g_meta[i] = m;
}

// ---------------------------------------------------------------- kernel 0b: bf16 split
__global__ void prep_kernel(const float* __restrict__ emb) {
    int idx = blockIdx.x * blockDim.x + threadIdx.x;     // fp32-pair index
    if (idx >= N_ANCH * 32) return;
    int row = idx >> 5, p = idx & 31;
    float2 v = reinterpret_cast<const float2*>(emb)[idx];
    __nv_bfloat16 h0 = __float2bfloat16(v.x);
    __nv_bfloat16 h1 = __float2bfloat16(v.y);
    __nv_bfloat16 l0 = __float2bfloat16(v.x - __bfloat162float(h0));
    __nv_bfloat16 l1 = __float2bfloat16(v.y - __bfloat162float(h1));
    unsigned int hp = ((unsigned int)__bfloat16_as_ushort(h1) << 16) |
                       (unsigned int)__bfloat16_as_ushort(h0);
    unsigned int lp = ((unsigned int)__bfloat16_as_ushort(l1) << 16) |
                       (unsigned int)__bfloat16_as_ushort(l0);
    g_ebf[row * 64 + p]      = hp;
    g_ebf[row * 64 + 32 + p] = lp;
}

// Async fill of one 128 x 192 bf16 tile (row stride ROWB).
// isA: K cols = [hi|lo|hi]  (src u128: c8<16 ? c8 : c8-16)
// !isA: K cols = [hi|hi|lo] (src u128: c8<8  ? c8 : c8-8)
__device__ __forceinline__ void fill_tile(uint32_t dst_sb, int row0, bool isA,
                                          int tid) {
    const char* src = reinterpret_cast<const char*>(g_ebf);
#pragma unroll
    for (int k = 0; k < 12; k++) {
        int idx = tid + k * THREADS;          // 128*24 = 3072 total
        int r = idx / 24, c8 = idx % 24;
        int s = isA ? (c8 < 16 ? c8 : c8 - 16) : (c8 < 8 ? c8 : c8 - 8);
        const char* sp = src + (((size_t)(row0 + r) << 4) + s) * 16;
        CP16(dst_sb + r * ROWB + c8 * 16, sp);
    }
}

// ---------------------------------------------------------------- kernel 1: mining (HMMA)
__global__ __launch_bounds__(THREADS, 1)
void mine_kernel(const int* __restrict__ tgt) {
    extern __shared__ char smem[];
    const uint32_t sb = smem_u32(smem);
    const int tid = threadIdx.x, wid = tid >> 5, lane = tid & 31;
    const int wm = wid >> 2, wn = wid & 3;       // 2 x 4 warp grid
    const int m_warp = wm * 64, n_warp = wn * 32;
    const int strip = blockIdx.x, split = blockIdx.y;
    const int i0 = strip * BM;
    const int j0 = split * (N_ANCH / JSPLIT);

    // Prologue: A (+B0) in group 0, B1 in group 1
    fill_tile(sb + OFF_A, i0, true, tid);
    fill_tile(sb + OFF_B0, j0, false, tid);
    CP_COMMIT();
    fill_tile(sb + OFF_B1, j0 + BN, false, tid);
    CP_COMMIT();

    // Per-thread anchor targets for the 8 row-slots (mt 0..3, half 0..1)
    int tslot[8];
#pragma unroll
    for (int mt = 0; mt < 4; mt++)
#pragma unroll
        for (int h = 0; h < 2; h++)
            tslot[mt * 2 + h] = tgt[i0 + m_warp + mt * 16 + (lane >> 2) + h * 8];

    const float INF_F = __int_as_float(0x7f800000);
    float mxv[8], mnv[8];
    int   mxj[8], mnj[8];
#pragma unroll
    for (int s = 0; s < 8; s++) {
        mxv[s] = -INF_F; mnv[s] = INF_F; mxj[s] = 0; mnj[s] = 0;
    }

    // ldmatrix lane base offsets (within a tile)
    const uint32_t lmoff = (uint32_t)(lane & 15) * ROWB + ((lane & 16) ? 16 : 0);
    const uint32_t aA = sb + OFF_A + m_warp * ROWB + lmoff;

    for (int t = 0; t < CHUNKS; t++) {
        const int b = t & 1;
        CP_WAIT1();
        __syncthreads();

        const uint32_t aB = sb + (b ? OFF_B1 : OFF_B0) + n_warp * ROWB + lmoff;

        float d[4][4][4];
#pragma unroll
        for (int mt = 0; mt < 4; mt++)
#pragma unroll
            for (int nt = 0; nt < 4; nt++)
#pragma unroll
                for (int e = 0; e < 4; e++) d[mt][nt][e] = 0.f;

#pragma unroll
        for (int s = 0; s < KSTEPS; s++) {
            uint32_t Af[4][4], Bf[2][4];
#pragma unroll
            for (int mt = 0; mt < 4; mt++)
                LDSM_X4(Af[mt], aA + mt * (16 * ROWB) + s * 32);
#pragma unroll
            for (int np = 0; np < 2; np++)
                LDSM_X4(Bf[np], aB + np * (16 * ROWB) + s * 32);
#pragma unroll
            for (int mt = 0; mt < 4; mt++)
#pragma unroll
                for (int nt = 0; nt < 4; nt++) {
                    int np = nt >> 1, sel = nt & 1;
                    MMA16816(d[mt][nt], Af[mt], Bf[np][sel], Bf[np][2 + sel]);
                }
        }

        // Fold this chunk's 64 dots into the argmax/argmin slots
        const int jb = j0 + t * BN;
#pragma unroll
        for (int nt = 0; nt < 4; nt++)
#pragma unroll
            for (int c = 0; c < 2; c++) {
                int j = jb + n_warp + nt * 8 + (lane & 3) * 2 + c;
                Meta m = g_meta[j];
#pragma unroll
                for (int mt = 0; mt < 4; mt++)
#pragma unroll
                    for (int h = 0; h < 2; h++) {
                        int sl = mt * 2 + h;
                        float key = fmaf(-2.0f, d[mt][nt][h * 2 + c], m.sq);
                        bool same = (m.tgt == tslot[sl]);
                        bool cp = same && (key > mxv[sl]);
                        mxv[sl] = cp ? key : mxv[sl];
                        mxj[sl] = cp ? j : mxj[sl];
                        bool cn = (!same) && (key < mnv[sl]);
                        mnv[sl] = cn ? key : mnv[sl];
                        mnj[sl] = cn ? j : mnj[sl];
                    }
            }

        __syncthreads();
        if (t + 2 < CHUNKS) {
            fill_tile(sb + (b ? OFF_B1 : OFF_B0), jb + 2 * BN, false, tid);
            CP_COMMIT();
        }
    }

    // Reduce across the 4 lanes of each quad (same rows, different cols)
#pragma unroll
    for (int s = 0; s < 8; s++) {
#pragma unroll
        for (int off = 1; off <= 2; off <<= 1) {
            float ov = __shfl_xor_sync(0xFFFFFFFFu, mxv[s], off);
            int   oj = __shfl_xor_sync(0xFFFFFFFFu, mxj[s], off);
            if (ov > mxv[s] || (ov == mxv[s] && oj < mxj[s])) {
                mxv[s] = ov; mxj[s] = oj;
            }
            ov = __shfl_xor_sync(0xFFFFFFFFu, mnv[s], off);
            oj = __shfl_xor_sync(0xFFFFFFFFu, mnj[s], off);
            if (ov < mnv[s] || (ov == mnv[s] && oj < mnj[s])) {
                mnv[s] = ov; mnj[s] = oj;
            }
        }
    }

    // Cross-warp combine through smem (overlay on B0 region)
    float* s_mv = reinterpret_cast<float*>(smem + OFF_B0);
    int*   s_mj = reinterpret_cast<int*>(smem + OFF_B0 + 2048);
    float* s_nv = reinterpret_cast<float*>(smem + OFF_B0 + 4096);
    int*   s_nj = reinterpret_cast<int*>(smem + OFF_B0 + 6144);
    __syncthreads();
    if ((lane & 3) == 0) {
#pragma unroll
        for (int mt = 0; mt < 4; mt++)
#pragma unroll
            for (int h = 0; h < 2; h++) {
                int sl = mt * 2 + h;
                int row = m_warp + mt * 16 + (lane >> 2) + h * 8;
                int o = wn * 128 + row;
                s_mv[o] = mxv[sl]; s_mj[o] = mxj[sl];
                s_nv[o] = mnv[sl]; s_nj[o] = mnj[sl];
            }
    }
    __syncthreads();
    if (tid < 128) {
        float bv = -INF_F, sv = INF_F;
        int bj = 0, sj = 0;
#pragma unroll
        for (int w = 0; w < 4; w++) {
            int o = w * 128 + tid;
            float v = s_mv[o]; int j = s_mj[o];
            if (v > bv || (v == bv && j < bj)) { bv = v; bj = j; }
            v = s_nv[o]; j = s_nj[o];
            if (v < sv || (v == sv && j < sj)) { sv = v; sj = j; }
        }
        const int oi = split * N_ANCH + i0 + tid;
        g_maxval[oi] = bv; g_maxidx[oi] = bj;
        g_minval[oi] = sv; g_minidx[oi] = sj;
    }
}

// ---------------------------------------------------------------- kernel 2: exact loss
__global__ void loss_kernel(const float* __restrict__ emb) {
    __shared__ float red[256];
    const int i = blockIdx.x * 256 + threadIdx.x;

    const float INF_F = __int_as_float(0x7f800000);
    float maxv = -INF_F; int p = 0;
    float minv =  INF_F; int n = 0;
#pragma unroll
    for (int s = 0; s < JSPLIT; s++) {
        const int o = s * N_ANCH + i;
        float v = g_maxval[o];
        if (v > maxv) { maxv = v; p = g_maxidx[o]; }
        v = g_minval[o];
        if (v < minv) { minv = v; n = g_minidx[o]; }
    }

    const float4* ei = reinterpret_cast<const float4*>(emb + (size_t)i * DIM);
    const float4* ep = reinterpret_cast<const float4*>(emb + (size_t)p * DIM);
    const float4* en = reinterpret_cast<const float4*>(emb + (size_t)n * DIM);
    float ap = 0.f, an = 0.f;
#pragma unroll
    for (int k = 0; k < DIM / 4; k++) {
        float4 vi = ei[k], vp = ep[k], vn = en[k];
        float dx;
        dx = vi.x - vp.x; ap += dx * dx;
        dx = vi.y - vp.y; ap += dx * dx;
        dx = vi.z - vp.z; ap += dx * dx;
        dx = vi.w - vp.w; ap += dx * dx;
        dx = vi.x - vn.x; an += dx * dx;
        dx = vi.y - vn.y; an += dx * dx;
        dx = vi.z - vn.z; an += dx * dx;
        dx = vi.w - vn.w; an += dx * dx;
    }
    float loss = fmaxf(ap - an + MARGIN_F, 0.0f);

    red[threadIdx.x] = loss;
    __syncthreads();
#pragma unroll
    for (int off = 128; off > 0; off >>= 1) {
        if (threadIdx.x < off) red[threadIdx.x] += red[threadIdx.x + off];
        __syncthreads();
    }
    if (threadIdx.x == 0) g_partial[blockIdx.x] = red[0];
}

// ---------------------------------------------------------------- kernel 3: mean
__global__ void final_kernel(float* __restrict__ out) {
    if (threadIdx.x == 0) {
        float s = 0.f;
#pragma unroll
        for (int k = 0; k < RBLOCKS; k++) s += g_partial[k];
        out[0] = s / (float)N_ANCH;
    }
}

// ----------------------------------------------------------------
extern "C" void kernel_launch(void* const* d_in, const int* in_sizes, int n_in,
                              void* d_out, int out_size) {
    const float* emb = (const float*)d_in[0];
    const int*   tgt = (const int*)d_in[1];
    float*       out = (float*)d_out;

    cudaFuncSetAttribute(mine_kernel, cudaFuncAttributeMaxDynamicSharedMemorySize,
                         SMEM_TOTAL);

    sqnorm_kernel<<<N_ANCH / 256, 256>>>(emb, tgt);
    prep_kernel<<<(N_ANCH * 32) / 256, 256>>>(emb);
    dim3 grid(STRIPS, JSPLIT);
    mine_kernel<<<grid, THREADS, SMEM_TOTAL>>>(tgt);
    loss_kernel<<<RBLOCKS, 256>>>(emb);
    final_kernel<<<1, 32>>>(out);
}

// round 6
// speedup vs baseline: 2.5380x; 1.0505x over previous
#include <cuda_runtime.h>
#include <cuda_bf16.h>
#include <cstdint>

// ---------------------------------------------------------------- constants
#define N_ANCH   8192
#define DIM      64
#define JSPLIT   4
#define STRIPS   64            // 8192 / 128
#define BM       128
#define BN       64
#define CHUNKS   32            // 2048 / 64 per split
#define KSTEPS   8             // K = 128 = [hi|lo] (A) x [hi|hi] (B)
#define THREADS  256
#define ROWB     272           // 128*2 + 16 pad (conflict-free ldmatrix)
#define MARGIN_F 0.5f
#define RBLOCKS  64

// SMEM layout (per CTA, 70656 B total)
#define OFF_A     0            // 128 x 272 = 34816
#define OFF_B0    34816        // 64 x 272 = 17408
#define OFF_B1    52224
#define OFF_META0 69632        // Meta[64] = 512
#define OFF_META1 70144
#define SMEM_TOTAL 70656

struct __align__(8) Meta { float sq; int tgt; };

// ---------------------------------------------------------------- scratch
__device__ unsigned int g_ebf[N_ANCH * 64];   // per row: 32 u32 hi | 32 u32 lo
__device__ Meta  g_meta[N_ANCH];
__device__ float g_maxval[JSPLIT * N_ANCH];
__device__ int   g_maxidx[JSPLIT * N_ANCH];
__device__ float g_minval[JSPLIT * N_ANCH];
__device__ int   g_minidx[JSPLIT * N_ANCH];
__device__ float g_partial[RBLOCKS];

// ---------------------------------------------------------------- PTX helpers
__device__ __forceinline__ uint32_t smem_u32(const void* p) {
    uint32_t a;
    asm("{ .reg .u64 t; cvta.to.shared.u64 t, %1; cvt.u32.u64 %0, t; }"
        : "=r"(a) : "l"(p));
    return a;
}
#define CP16(d, s) \
    asm volatile("cp.async.cg.shared.global [%0], [%1], 16;" \
                 :: "r"(d), "l"(s) : "memory")
#define CP_COMMIT() asm volatile("cp.async.commit_group;" ::: "memory")
#define CP_WAIT1()  asm volatile("cp.async.wait_group 1;" ::: "memory")

#define LDSM_X4(R, addr) \
    asm volatile("ldmatrix.sync.aligned.m8n8.x4.shared.b16 {%0,%1,%2,%3}, [%4];" \
                 : "=r"((R)[0]), "=r"((R)[1]), "=r"((R)[2]), "=r"((R)[3]) \
                 : "r"(addr))

#define MMA16816(D, A, B0, B1) \
    asm volatile("mma.sync.aligned.m16n8k16.row.col.f32.bf16.bf16.f32 " \
                 "{%0,%1,%2,%3},{%4,%5,%6,%7},{%8,%9},{%0,%1,%2,%3};" \
                 : "+f"((D)[0]), "+f"((D)[1]), "+f"((D)[2]), "+f"((D)[3]) \
                 : "r"((A)[0]), "r"((A)[1]), "r"((A)[2]), "r"((A)[3]), \
                   "r"(B0), "r"(B1))

// ---------------------------------------------------------------- kernel 0a: norms+meta
__global__ void sqnorm_kernel(const float* __restrict__ emb,
                              const int* __restrict__ tgt) {
    int i = blockIdx.x * blockDim.x + threadIdx.x;
    if (i >= N_ANCH) return;
    const float4* r = reinterpret_cast<const float4*>(emb + (size_t)i * DIM);
    float s = 0.f;
#pragma unroll
    for (int k = 0; k < DIM / 4; k++) {
        float4 v = r[k];
        s += v.x * v.x + v.y * v.y + v.z * v.z + v.w * v.w;
    }
    Meta m; m.sq = s; m.tgt = tgt[i];
    g_meta[i] = m;
}

// ---------------------------------------------------------------- kernel 0b: bf16 split
__global__ void prep_kernel(const float* __restrict__ emb) {
    int idx = blockIdx.x * blockDim.x + threadIdx.x;     // fp32-pair index
    if (idx >= N_ANCH * 32) return;
    int row = idx >> 5, p = idx & 31;
    float2 v = reinterpret_cast<const float2*>(emb)[idx];
    __nv_bfloat16 h0 = __float2bfloat16(v.x);
    __nv_bfloat16 h1 = __float2bfloat16(v.y);
    __nv_bfloat16 l0 = __float2bfloat16(v.x - __bfloat162float(h0));
    __nv_bfloat16 l1 = __float2bfloat16(v.y - __bfloat162float(h1));
    unsigned int hp = ((unsigned int)__bfloat16_as_ushort(h1) << 16) |
                       (unsigned int)__bfloat16_as_ushort(h0);
    unsigned int lp = ((unsigned int)__bfloat16_as_ushort(l1) << 16) |
                       (unsigned int)__bfloat16_as_ushort(l0);
    g_ebf[row * 64 + p]      = hp;
    g_ebf[row * 64 + 32 + p] = lp;
}

// A tile: 128 rows x [hi(128B) | lo(128B)] == g_ebf row layout verbatim.
__device__ __forceinline__ void fill_a(uint32_t dst_sb, int row0, int tid) {
    const char* src = reinterpret_cast<const char*>(g_ebf);
#pragma unroll
    for (int k = 0; k < 8; k++) {
        int idx = tid + k * THREADS;          // 128*16 = 2048
        int r = idx >> 4, c8 = idx & 15;
        CP16(dst_sb + r * ROWB + c8 * 16,
             src + (((size_t)(row0 + r) << 4) + c8) * 16);
    }
}
// B tile: 64 rows x [hi | hi].
__device__ __forceinline__ void fill_b(uint32_t dst_sb, int row0, int tid) {
    const char* src = reinterpret_cast<const char*>(g_ebf);
#pragma unroll
    for (int k = 0; k < 4; k++) {
        int idx = tid + k * THREADS;          // 64*16 = 1024
        int r = idx >> 4, c8 = idx & 15;
        CP16(dst_sb + r * ROWB + c8 * 16,
             src + (((size_t)(row0 + r) << 4) + (c8 & 7)) * 16);
    }
}

// ---------------------------------------------------------------- kernel 1: mining (HMMA)
__global__ __launch_bounds__(THREADS, 2)
void mine_kernel(const int* __restrict__ tgt) {
    extern __shared__ char smem[];
    const uint32_t sb = smem_u32(smem);
    const int tid = threadIdx.x, wid = tid >> 5, lane = tid & 31;
    const int wm = wid >> 1, wn = wid & 1;       // 4 x 2 warp grid
    const int m_warp = wm * 32, n_warp = wn * 32;
    const int strip = blockIdx.x, split = blockIdx.y;
    const int i0 = strip * BM;
    const int j0 = split * (N_ANCH / JSPLIT);

    Meta* meta0 = reinterpret_cast<Meta*>(smem + OFF_META0);
    Meta* meta1 = reinterpret_cast<Meta*>(smem + OFF_META1);

    // Prologue: group0 = A + B(0); group1 = B(1)
    fill_a(sb + OFF_A, i0, tid);
    fill_b(sb + OFF_B0, j0, tid);
    if (tid < BN) meta0[tid] = g_meta[j0 + tid];
    CP_COMMIT();
    fill_b(sb + OFF_B1, j0 + BN, tid);
    if (tid < BN) meta1[tid] = g_meta[j0 + BN + tid];
    CP_COMMIT();

    // Anchor targets for the 4 row-slots (mt 0..1, half 0..1)
    int tslot[4];
#pragma unroll
    for (int mt = 0; mt < 2; mt++)
#pragma unroll
        for (int h = 0; h < 2; h++)
            tslot[mt * 2 + h] = tgt[i0 + m_warp + mt * 16 + (lane >> 2) + h * 8];

    const float INF_F = __int_as_float(0x7f800000);
    float mxv[4], mnv[4];
    int   mxj[4], mnj[4];
#pragma unroll
    for (int s = 0; s < 4; s++) {
        mxv[s] = -INF_F; mnv[s] = INF_F; mxj[s] = 0; mnj[s] = 0;
    }

    const uint32_t lmoff = (uint32_t)(lane & 15) * ROWB + ((lane & 16) ? 16 : 0);
    const uint32_t aA = sb + OFF_A + m_warp * ROWB + lmoff;

    for (int t = 0; t < CHUNKS; t++) {
        const int b = t & 1;
        CP_WAIT1();
        __syncthreads();

        const uint32_t aB = sb + (b ? OFF_B1 : OFF_B0) + n_warp * ROWB + lmoff;
        Meta* meta = b ? meta1 : meta0;

        float d[2][4][4];
#pragma unroll
        for (int mt = 0; mt < 2; mt++)
#pragma unroll
            for (int nt = 0; nt < 4; nt++)
#pragma unroll
                for (int e = 0; e < 4; e++) d[mt][nt][e] = 0.f;

#pragma unroll
        for (int s = 0; s < KSTEPS; s++) {
            uint32_t Af[2][4], Bf[2][4];
#pragma unroll
            for (int mt = 0; mt < 2; mt++)
                LDSM_X4(Af[mt], aA + mt * (16 * ROWB) + s * 32);
#pragma unroll
            for (int np = 0; np < 2; np++)
                LDSM_X4(Bf[np], aB + np * (16 * ROWB) + s * 32);
#pragma unroll
            for (int mt = 0; mt < 2; mt++)
#pragma unroll
                for (int nt = 0; nt < 4; nt++) {
                    int np = nt >> 1, sel = nt & 1;
                    MMA16816(d[mt][nt], Af[mt], Bf[np][sel], Bf[np][2 + sel]);
                }
        }

        // Fold 32 dots into the argmax/argmin slots
        const int jb = j0 + t * BN;
#pragma unroll
        for (int nt = 0; nt < 4; nt++)
#pragma unroll
            for (int c = 0; c < 2; c++) {
                int jl = n_warp + nt * 8 + (lane & 3) * 2 + c;
                int j = jb + jl;
                Meta m = meta[jl];
#pragma unroll
                for (int mt = 0; mt < 2; mt++)
#pragma unroll
                    for (int h = 0; h < 2; h++) {
                        int sl = mt * 2 + h;
                        float key = fmaf(-2.0f, d[mt][nt][h * 2 + c], m.sq);
                        bool same = (m.tgt == tslot[sl]);
                        bool cp = same && (key > mxv[sl]);
                        mxv[sl] = cp ? key : mxv[sl];
                        mxj[sl] = cp ? j : mxj[sl];
                        bool cn = (!same) && (key < mnv[sl]);
                        mnv[sl] = cn ? key : mnv[sl];
                        mnj[sl] = cn ? j : mnj[sl];
                    }
            }

        __syncthreads();
        if (t + 2 < CHUNKS) {
            fill_b(sb + (b ? OFF_B1 : OFF_B0), jb + 2 * BN, tid);
            if (tid < BN) (b ? meta1 : meta0)[tid] = g_meta[jb + 2 * BN + tid];
            CP_COMMIT();
        }
    }

    // Reduce across the 4 lanes of each quad (same rows, different j)
#pragma unroll
    for (int s = 0; s < 4; s++) {
#pragma unroll
        for (int off = 1; off <= 2; off <<= 1) {
            float ov = __shfl_xor_sync(0xFFFFFFFFu, mxv[s], off);
            int   oj = __shfl_xor_sync(0xFFFFFFFFu, mxj[s], off);
            if (ov > mxv[s] || (ov == mxv[s] && oj < mxj[s])) {
                mxv[s] = ov; mxj[s] = oj;
            }
            ov = __shfl_xor_sync(0xFFFFFFFFu, mnv[s], off);
            oj = __shfl_xor_sync(0xFFFFFFFFu, mnj[s], off);
            if (ov < mnv[s] || (ov == mnv[s] && oj < mnj[s])) {
                mnv[s] = ov; mnj[s] = oj;
            }
        }
    }

    // Cross-warp combine through smem (overlay on B0 region)
    float* s_mv = reinterpret_cast<float*>(smem + OFF_B0);
    int*   s_mj = reinterpret_cast<int*>(smem + OFF_B0 + 1024);
    float* s_nv = reinterpret_cast<float*>(smem + OFF_B0 + 2048);
    int*   s_nj = reinterpret_cast<int*>(smem + OFF_B0 + 3072);
    __syncthreads();
    if ((lane & 3) == 0) {
#pragma unroll
        for (int mt = 0; mt < 2; mt++)
#pragma unroll
            for (int h = 0; h < 2; h++) {
                int sl = mt * 2 + h;
                int row = m_warp + mt * 16 + (lane >> 2) + h * 8;
                int o = wn * 128 + row;
                s_mv[o] = mxv[sl]; s_mj[o] = mxj[sl];
                s_nv[o] = mnv[sl]; s_nj[o] = mnj[sl];
            }
    }
    __syncthreads();
    if (tid < 128) {
        float bv = -INF_F, sv = INF_F;
        int bj = 0, sj = 0;
#pragma unroll
        for (int w = 0; w < 2; w++) {
            int o = w * 128 + tid;
            float v = s_mv[o]; int j = s_mj[o];
            if (v > bv || (v == bv && j < bj)) { bv = v; bj = j; }
            v = s_nv[o]; j = s_nj[o];
            if (v < sv || (v == sv && j < sj)) { sv = v; sj = j; }
        }
        const int oi = split * N_ANCH + i0 + tid;
        g_maxval[oi] = bv; g_maxidx[oi] = bj;
        g_minval[oi] = sv; g_minidx[oi] = sj;
    }
}

// ---------------------------------------------------------------- kernel 2: exact loss
__global__ void loss_kernel(const float* __restrict__ emb) {
    __shared__ float red[128];
    const int i = blockIdx.x * 128 + threadIdx.x;

    const float INF_F = __int_as_float(0x7f800000);
    float maxv = -INF_F; int p = 0;
    float minv =  INF_F; int n = 0;
#pragma unroll
    for (int s = 0; s < JSPLIT; s++) {
        const int o = s * N_ANCH + i;
        float v = g_maxval[o];
        if (v > maxv) { maxv = v; p = g_maxidx[o]; }
        v = g_minval[o];
        if (v < minv) { minv = v; n = g_minidx[o]; }
    }

    const float4* ei = reinterpret_cast<const float4*>(emb + (size_t)i * DIM);
    const float4* ep = reinterpret_cast<const float4*>(emb + (size_t)p * DIM);
    const float4* en = reinterpret_cast<const float4*>(emb + (size_t)n * DIM);
    float ap = 0.f, an = 0.f;
#pragma unroll
    for (int k = 0; k < DIM / 4; k++) {
        float4 vi = ei[k], vp = ep[k], vn = en[k];
        float dx;
        dx = vi.x - vp.x; ap += dx * dx;
        dx = vi.y - vp.y; ap += dx * dx;
        dx = vi.z - vp.z; ap += dx * dx;
        dx = vi.w - vp.w; ap += dx * dx;
        dx = vi.x - vn.x; an += dx * dx;
        dx = vi.y - vn.y; an += dx * dx;
        dx = vi.z - vn.z; an += dx * dx;
        dx = vi.w - vn.w; an += dx * dx;
    }
    float loss = fmaxf(ap - an + MARGIN_F, 0.0f);

    red[threadIdx.x] = loss;
    __syncthreads();
#pragma unroll
    for (int off = 64; off > 0; off >>= 1) {
        if (threadIdx.x < off) red[threadIdx.x] += red[threadIdx.x + off];
        __syncthreads();
    }
    if (threadIdx.x == 0) g_partial[blockIdx.x] = red[0];
}

// ---------------------------------------------------------------- kernel 3: mean
__global__ void final_kernel(float* __restrict__ out) {
    if (threadIdx.x == 0) {
        float s = 0.f;
#pragma unroll
        for (int k = 0; k < RBLOCKS; k++) s += g_partial[k];
        out[0] = s / (float)N_ANCH;
    }
}

// ----------------------------------------------------------------
extern "C" void kernel_launch(void* const* d_in, const int* in_sizes, int n_in,
                              void* d_out, int out_size) {
    const float* emb = (const float*)d_in[0];
    const int*   tgt = (const int*)d_in[1];
    float*       out = (float*)d_out;

    cudaFuncSetAttribute(mine_kernel, cudaFuncAttributeMaxDynamicSharedMemorySize,
                         SMEM_TOTAL);

    sqnorm_kernel<<<N_ANCH / 256, 256>>>(emb, tgt);
    prep_kernel<<<(N_ANCH * 32) / 256, 256>>>(emb);
    dim3 grid(STRIPS, JSPLIT);
    mine_kernel<<<grid, THREADS, SMEM_TOTAL>>>(tgt);
    loss_kernel<<<RBLOCKS, 128>>>(emb);
    final_kernel<<<1, 32>>>(out);
}

// round 7
// speedup vs baseline: 4.2721x; 1.6833x over previous
#include <cuda_runtime.h>
#include <cuda_bf16.h>
#include <cstdint>

// ---------------------------------------------------------------- constants
#define N_ANCH   8192
#define DIM      64
#define JSPLIT   4
#define STRIPS   64            // 8192 / 128
#define BM       128
#define BN       64
#define CHUNKS   32            // 2048 / 64 per split
#define KSTEPS   4             // K = 64 (hi only)
#define THREADS  256
#define ROWB     144           // 64*2 + 16 pad (conflict-free ldmatrix)
#define MARGIN_F 0.5f
#define RBLOCKS  128

// SMEM layout (per CTA)
#define OFF_A     0            // 128 x 144 = 18432
#define OFF_B0    18432        // 64 x 144 = 9216
#define OFF_B1    27648
#define OFF_META0 36864        // Meta[64] = 512
#define OFF_META1 37376
#define SMEM_TOTAL 37888

struct __align__(8) Meta { float sq; int tgt; };

// ---------------------------------------------------------------- scratch
__device__ unsigned int g_ebf[N_ANCH * 32];   // bf16 hi pairs, 128B per row
__device__ Meta  g_meta[N_ANCH];
__device__ float g_maxval[JSPLIT * N_ANCH];
__device__ int   g_maxidx[JSPLIT * N_ANCH];
__device__ float g_minval[JSPLIT * N_ANCH];
__device__ int   g_minidx[JSPLIT * N_ANCH];
__device__ float g_partial[RBLOCKS];
__device__ unsigned int g_count;

// ---------------------------------------------------------------- PTX helpers
__device__ __forceinline__ uint32_t smem_u32(const void* p) {
    uint32_t a;
    asm("{ .reg .u64 t; cvta.to.shared.u64 t, %1; cvt.u32.u64 %0, t; }"
        : "=r"(a) : "l"(p));
    return a;
}
#define CP16(d, s) \
    asm volatile("cp.async.cg.shared.global [%0], [%1], 16;" \
                 :: "r"(d), "l"(s) : "memory")
#define CP_COMMIT() asm volatile("cp.async.commit_group;" ::: "memory")
#define CP_WAIT1()  asm volatile("cp.async.wait_group 1;" ::: "memory")

#define LDSM_X4(R, addr) \
    asm volatile("ldmatrix.sync.aligned.m8n8.x4.shared.b16 {%0,%1,%2,%3}, [%4];" \
                 : "=r"((R)[0]), "=r"((R)[1]), "=r"((R)[2]), "=r"((R)[3]) \
                 : "r"(addr))

#define MMA16816(D, A, B0, B1) \
    asm volatile("mma.sync.aligned.m16n8k16.row.col.f32.bf16.bf16.f32 " \
                 "{%0,%1,%2,%3},{%4,%5,%6,%7},{%8,%9},{%0,%1,%2,%3};" \
                 : "+f"((D)[0]), "+f"((D)[1]), "+f"((D)[2]), "+f"((D)[3]) \
                 : "r"((A)[0]), "r"((A)[1]), "r"((A)[2]), "r"((A)[3]), \
                   "r"(B0), "r"(B1))

// ---------------------------------------------------------------- kernel 0: prep
// 8 threads per row: bf16-hi pack + sq norm + meta. Also resets g_count.
__global__ void prep_kernel(const float* __restrict__ emb,
                            const int* __restrict__ tgt) {
    if (blockIdx.x == 0 && threadIdx.x == 0) g_count = 0;
    int idx = blockIdx.x * blockDim.x + threadIdx.x;
    int row = idx >> 3, sub = idx & 7;
    const float4* src = reinterpret_cast<const float4*>(emb);
    float4 v0 = src[row * 16 + sub * 2];
    float4 v1 = src[row * 16 + sub * 2 + 1];

    unsigned int h[4];
    h[0] = ((unsigned)__bfloat16_as_ushort(__float2bfloat16(v0.y)) << 16) |
            (unsigned)__bfloat16_as_ushort(__float2bfloat16(v0.x));
    h[1] = ((unsigned)__bfloat16_as_ushort(__float2bfloat16(v0.w)) << 16) |
            (unsigned)__bfloat16_as_ushort(__float2bfloat16(v0.z));
    h[2] = ((unsigned)__bfloat16_as_ushort(__float2bfloat16(v1.y)) << 16) |
            (unsigned)__bfloat16_as_ushort(__float2bfloat16(v1.x));
    h[3] = ((unsigned)__bfloat16_as_ushort(__float2bfloat16(v1.w)) << 16) |
            (unsigned)__bfloat16_as_ushort(__float2bfloat16(v1.z));
    reinterpret_cast<uint4*>(g_ebf)[row * 8 + sub] =
        make_uint4(h[0], h[1], h[2], h[3]);

    float s = v0.x * v0.x + v0.y * v0.y + v0.z * v0.z + v0.w * v0.w +
              v1.x * v1.x + v1.y * v1.y + v1.z * v1.z + v1.w * v1.w;
    s += __shfl_xor_sync(0xFFFFFFFFu, s, 1);
    s += __shfl_xor_sync(0xFFFFFFFFu, s, 2);
    s += __shfl_xor_sync(0xFFFFFFFFu, s, 4);
    if (sub == 0) { Meta m; m.sq = s; m.tgt = tgt[row]; g_meta[row] = m; }
}

// A tile: 128 rows x 128B (hi). B tile: 64 rows x 128B.
__device__ __forceinline__ void fill_a(uint32_t dst_sb, int row0, int tid) {
    const char* src = reinterpret_cast<const char*>(g_ebf);
#pragma unroll
    for (int k = 0; k < 4; k++) {
        int idx = tid + k * THREADS;          // 128*8 = 1024
        int r = idx >> 3, c8 = idx & 7;
        CP16(dst_sb + r * ROWB + c8 * 16,
             src + (size_t)(row0 + r) * 128 + c8 * 16);
    }
}
__device__ __forceinline__ void fill_b(uint32_t dst_sb, int row0, int tid) {
    const char* src = reinterpret_cast<const char*>(g_ebf);
#pragma unroll
    for (int k = 0; k < 2; k++) {
        int idx = tid + k * THREADS;          // 64*8 = 512
        int r = idx >> 3, c8 = idx & 7;
        CP16(dst_sb + r * ROWB + c8 * 16,
             src + (size_t)(row0 + r) * 128 + c8 * 16);
    }
}

// ---------------------------------------------------------------- kernel 1: mining
__global__ __launch_bounds__(THREADS, 2)
void mine_kernel(const int* __restrict__ tgt) {
    extern __shared__ char smem[];
    const uint32_t sb = smem_u32(smem);
    const int tid = threadIdx.x, wid = tid >> 5, lane = tid & 31;
    const int wm = wid >> 1, wn = wid & 1;       // 4 x 2 warp grid
    const int m_warp = wm * 32, n_warp = wn * 32;
    const int strip = blockIdx.x, split = blockIdx.y;
    const int i0 = strip * BM;
    const int j0 = split * (N_ANCH / JSPLIT);

    Meta* meta0 = reinterpret_cast<Meta*>(smem + OFF_META0);
    Meta* meta1 = reinterpret_cast<Meta*>(smem + OFF_META1);

    // Prologue: group0 = A + B(0); group1 = B(1)
    fill_a(sb + OFF_A, i0, tid);
    fill_b(sb + OFF_B0, j0, tid);
    if (tid < BN) meta0[tid] = g_meta[j0 + tid];
    CP_COMMIT();
    fill_b(sb + OFF_B1, j0 + BN, tid);
    if (tid < BN) meta1[tid] = g_meta[j0 + BN + tid];
    CP_COMMIT();

    int tslot[4];
#pragma unroll
    for (int mt = 0; mt < 2; mt++)
#pragma unroll
        for (int h = 0; h < 2; h++)
            tslot[mt * 2 + h] = tgt[i0 + m_warp + mt * 16 + (lane >> 2) + h * 8];

    const float INF_F = __int_as_float(0x7f800000);
    float mxv[4], mnv[4];
    int   mxj[4], mnj[4];
#pragma unroll
    for (int s = 0; s < 4; s++) {
        mxv[s] = -INF_F; mnv[s] = INF_F; mxj[s] = 0; mnj[s] = 0;
    }

    const uint32_t lmoff = (uint32_t)(lane & 15) * ROWB + ((lane & 16) ? 16 : 0);
    const uint32_t aA = sb + OFF_A + m_warp * ROWB + lmoff;

    // Wait for A + B0, then hoist all A fragments (loop-invariant)
    CP_WAIT1();
    __syncthreads();
    uint32_t Af[2][KSTEPS][4];
#pragma unroll
    for (int mt = 0; mt < 2; mt++)
#pragma unroll
        for (int s = 0; s < KSTEPS; s++)
            LDSM_X4(Af[mt][s], aA + mt * (16 * ROWB) + s * 32);

    for (int t = 0; t < CHUNKS; t++) {
        const int b = t & 1;
        if (t > 0) { CP_WAIT1(); __syncthreads(); }

        const uint32_t aB = sb + (b ? OFF_B1 : OFF_B0) + n_warp * ROWB + lmoff;
        Meta* meta = b ? meta1 : meta0;

        float d[2][4][4];
#pragma unroll
        for (int mt = 0; mt < 2; mt++)
#pragma unroll
            for (int nt = 0; nt < 4; nt++)
#pragma unroll
                for (int e = 0; e < 4; e++) d[mt][nt][e] = 0.f;

#pragma unroll
        for (int s = 0; s < KSTEPS; s++) {
            uint32_t Bf[2][4];
#pragma unroll
            for (int np = 0; np < 2; np++)
                LDSM_X4(Bf[np], aB + np * (16 * ROWB) + s * 32);
#pragma unroll
            for (int mt = 0; mt < 2; mt++)
#pragma unroll
                for (int nt = 0; nt < 4; nt++) {
                    int np = nt >> 1, sel = nt & 1;
                    MMA16816(d[mt][nt], Af[mt][s], Bf[np][sel], Bf[np][2 + sel]);
                }
        }

        const int jb = j0 + t * BN;
#pragma unroll
        for (int nt = 0; nt < 4; nt++)
#pragma unroll
            for (int c = 0; c < 2; c++) {
                int jl = n_warp + nt * 8 + (lane & 3) * 2 + c;
                int j = jb + jl;
                Meta m = meta[jl];
#pragma unroll
                for (int mt = 0; mt < 2; mt++)
#pragma unroll
                    for (int h = 0; h < 2; h++) {
                        int sl = mt * 2 + h;
                        float key = fmaf(-2.0f, d[mt][nt][h * 2 + c], m.sq);
                        bool same = (m.tgt == tslot[sl]);
                        float kpos = same ? key : -INF_F;
                        float kneg = same ? INF_F : key;
                        bool cp = kpos > mxv[sl];
                        mxv[sl] = fmaxf(mxv[sl], kpos);
                        mxj[sl] = cp ? j : mxj[sl];
                        bool cn = kneg < mnv[sl];
                        mnv[sl] = fminf(mnv[sl], kneg);
                        mnj[sl] = cn ? j : mnj[sl];
                    }
            }

        __syncthreads();
        if (t + 2 < CHUNKS) {
            fill_b(sb + (b ? OFF_B1 : OFF_B0), jb + 2 * BN, tid);
            if (tid < BN) (b ? meta1 : meta0)[tid] = g_meta[jb + 2 * BN + tid];
            CP_COMMIT();
        }
    }

    // Reduce across the 4 lanes of each quad (same rows, different j)
#pragma unroll
    for (int s = 0; s < 4; s++) {
#pragma unroll
        for (int off = 1; off <= 2; off <<= 1) {
            float ov = __shfl_xor_sync(0xFFFFFFFFu, mxv[s], off);
            int   oj = __shfl_xor_sync(0xFFFFFFFFu, mxj[s], off);
            if (ov > mxv[s] || (ov == mxv[s] && oj < mxj[s])) {
                mxv[s] = ov; mxj[s] = oj;
            }
            ov = __shfl_xor_sync(0xFFFFFFFFu, mnv[s], off);
            oj = __shfl_xor_sync(0xFFFFFFFFu, mnj[s], off);
            if (ov < mnv[s] || (ov == mnv[s] && oj < mnj[s])) {
                mnv[s] = ov; mnj[s] = oj;
            }
        }
    }

    // Cross-warp combine through smem (overlay on B0 region)
    float* s_mv = reinterpret_cast<float*>(smem + OFF_B0);
    int*   s_mj = reinterpret_cast<int*>(smem + OFF_B0 + 1024);
    float* s_nv = reinterpret_cast<float*>(smem + OFF_B0 + 2048);
    int*   s_nj = reinterpret_cast<int*>(smem + OFF_B0 + 3072);
    __syncthreads();
    if ((lane & 3) == 0) {
#pragma unroll
        for (int mt = 0; mt < 2; mt++)
#pragma unroll
            for (int h = 0; h < 2; h++) {
                int sl = mt * 2 + h;
                int row = m_warp + mt * 16 + (lane >> 2) + h * 8;
                int o = wn * 128 + row;
                s_mv[o] = mxv[sl]; s_mj[o] = mxj[sl];
                s_nv[o] = mnv[sl]; s_nj[o] = mnj[sl];
            }
    }
    __syncthreads();
    if (tid < 128) {
        float bv = -INF_F, sv = INF_F;
        int bj = 0, sj = 0;
#pragma unroll
        for (int w = 0; w < 2; w++) {
            int o = w * 128 + tid;
            float v = s_mv[o]; int j = s_mj[o];
            if (v > bv || (v == bv && j < bj)) { bv = v; bj = j; }
            v = s_nv[o]; j = s_nj[o];
            if (v < sv || (v == sv && j < sj)) { sv = v; sj = j; }
        }
        const int oi = split * N_ANCH + i0 + tid;
        g_maxval[oi] = bv; g_maxidx[oi] = bj;
        g_minval[oi] = sv; g_minidx[oi] = sj;
    }
}

// ---------------------------------------------------------------- kernel 2: loss + mean
// 4 threads per anchor; deterministic last-block final sum.
__global__ void loss_kernel(const float* __restrict__ emb,
                            float* __restrict__ out) {
    __shared__ float red[64];
    const int tid = threadIdx.x;
    const int i = blockIdx.x * 64 + (tid >> 2);
    const int sub = tid & 3;

    const float INF_F = __int_as_float(0x7f800000);
    float maxv = -INF_F; int p = 0;
    float minv =  INF_F; int n = 0;
#pragma unroll
    for (int s = 0; s < JSPLIT; s++) {
        const int o = s * N_ANCH + i;
        float v = g_maxval[o];
        if (v > maxv) { maxv = v; p = g_maxidx[o]; }
        v = g_minval[o];
        if (v < minv) { minv = v; n = g_minidx[o]; }
    }

    const float4* ei = reinterpret_cast<const float4*>(emb + (size_t)i * DIM) + sub * 4;
    const float4* ep = reinterpret_cast<const float4*>(emb + (size_t)p * DIM) + sub * 4;
    const float4* en = reinterpret_cast<const float4*>(emb + (size_t)n * DIM) + sub * 4;
    float ap = 0.f, an = 0.f;
#pragma unroll
    for (int k = 0; k < 4; k++) {
        float4 vi = ei[k], vp = ep[k], vn = en[k];
        float dx;
        dx = vi.x - vp.x; ap += dx * dx;
        dx = vi.y - vp.y; ap += dx * dx;
        dx = vi.z - vp.z; ap += dx * dx;
        dx = vi.w - vp.w; ap += dx * dx;
        dx = vi.x - vn.x; an += dx * dx;
        dx = vi.y - vn.y; an += dx * dx;
        dx = vi.z - vn.z; an += dx * dx;
        dx = vi.w - vn.w; an += dx * dx;
    }
    float v = ap - an;
    v += __shfl_xor_sync(0xFFFFFFFFu, v, 1);
    v += __shfl_xor_sync(0xFFFFFFFFu, v, 2);
    if (sub == 0) red[tid >> 2] = fmaxf(v + MARGIN_F, 0.0f);
    __syncthreads();

#pragma unroll
    for (int off = 32; off > 0; off >>= 1) {
        if (tid < off) red[tid] += red[tid + off];
        __syncthreads();
    }
    if (tid == 0) {
        g_partial[blockIdx.x] = red[0];
        __threadfence();
        unsigned int ticket = atomicAdd(&g_count, 1u);
        if (ticket == RBLOCKS - 1) {            // last block: fixed-order sum
            float s = 0.f;
#pragma unroll
            for (int k = 0; k < RBLOCKS; k++) s += g_partial[k];
            out[0] = s / (float)N_ANCH;
        }
    }
}

// ----------------------------------------------------------------
extern "C" void kernel_launch(void* const* d_in, const int* in_sizes, int n_in,
                              void* d_out, int out_size) {
    const float* emb = (const float*)d_in[0];
    const int*   tgt = (const int*)d_in[1];
    float*       out = (float*)d_out;

    cudaFuncSetAttribute(mine_kernel, cudaFuncAttributeMaxDynamicSharedMemorySize,
                         SMEM_TOTAL);

    prep_kernel<<<(N_ANCH * 8) / 256, 256>>>(emb, tgt);
    dim3 grid(STRIPS, JSPLIT);
    mine_kernel<<<grid, THREADS, SMEM_TOTAL>>>(tgt);
    loss_kernel<<<RBLOCKS, 256>>>(emb, out);
}

// round 8
// speedup vs baseline: 4.9572x; 1.1604x over previous
#include <cuda_runtime.h>
#include <cuda_bf16.h>
#include <cstdint>

// ---------------------------------------------------------------- constants
#define N_ANCH   8192
#define DIM      64
#define JSPLIT   8
#define STRIPS   64            // 8192 / 128
#define BM       128
#define BN       64
#define CHUNKS   16            // 1024 / 64 per split
#define KSTEPS   4             // K = 64 (hi only)
#define THREADS  256
#define ROWB     144           // 64*2 + 16 pad (conflict-free ldmatrix)
#define MARGIN_F 0.5f
#define RBLOCKS  128

// SMEM layout (per CTA): A 18432 | B x3 9216 | meta x3 512
#define OFF_A     0
#define OFF_B     18432
#define BSTRIDE   9216
#define OFF_META  46080
#define MSTRIDE   512
#define SMEM_TOTAL 47616

struct __align__(8) Meta { float sq; int tgt; };

// ---------------------------------------------------------------- scratch
__device__ unsigned int g_ebf[N_ANCH * 32];   // bf16 hi pairs, 128B per row
__device__ Meta  g_meta[N_ANCH];
__device__ float g_maxval[JSPLIT * N_ANCH];
__device__ int   g_maxidx[JSPLIT * N_ANCH];
__device__ float g_minval[JSPLIT * N_ANCH];
__device__ int   g_minidx[JSPLIT * N_ANCH];
__device__ float g_partial[RBLOCKS];
__device__ unsigned int g_count;

// ---------------------------------------------------------------- PTX helpers
__device__ __forceinline__ uint32_t smem_u32(const void* p) {
    uint32_t a;
    asm("{ .reg .u64 t; cvta.to.shared.u64 t, %1; cvt.u32.u64 %0, t; }"
        : "=r"(a) : "l"(p));
    return a;
}
#define CP16(d, s) \
    asm volatile("cp.async.cg.shared.global [%0], [%1], 16;" \
                 :: "r"(d), "l"(s) : "memory")
#define CP_COMMIT() asm volatile("cp.async.commit_group;" ::: "memory")
#define CP_WAIT1()  asm volatile("cp.async.wait_group 1;" ::: "memory")

#define LDSM_X4(R, addr) \
    asm volatile("ldmatrix.sync.aligned.m8n8.x4.shared.b16 {%0,%1,%2,%3}, [%4];" \
                 : "=r"((R)[0]), "=r"((R)[1]), "=r"((R)[2]), "=r"((R)[3]) \
                 : "r"(addr))

#define MMA16816(D, A, B0, B1) \
    asm volatile("mma.sync.aligned.m16n8k16.row.col.f32.bf16.bf16.f32 " \
                 "{%0,%1,%2,%3},{%4,%5,%6,%7},{%8,%9},{%0,%1,%2,%3};" \
                 : "+f"((D)[0]), "+f"((D)[1]), "+f"((D)[2]), "+f"((D)[3]) \
                 : "r"((A)[0]), "r"((A)[1]), "r"((A)[2]), "r"((A)[3]), \
                   "r"(B0), "r"(B1))

// ---------------------------------------------------------------- kernel 0: prep
__global__ void prep_kernel(const float* __restrict__ emb,
                            const int* __restrict__ tgt) {
    if (blockIdx.x == 0 && threadIdx.x == 0) g_count = 0;
    int idx = blockIdx.x * blockDim.x + threadIdx.x;
    int row = idx >> 3, sub = idx & 7;
    const float4* src = reinterpret_cast<const float4*>(emb);
    float4 v0 = src[row * 16 + sub * 2];
    float4 v1 = src[row * 16 + sub * 2 + 1];

    unsigned int h[4];
    h[0] = ((unsigned)__bfloat16_as_ushort(__float2bfloat16(v0.y)) << 16) |
            (unsigned)__bfloat16_as_ushort(__float2bfloat16(v0.x));
    h[1] = ((unsigned)__bfloat16_as_ushort(__float2bfloat16(v0.w)) << 16) |
            (unsigned)__bfloat16_as_ushort(__float2bfloat16(v0.z));
    h[2] = ((unsigned)__bfloat16_as_ushort(__float2bfloat16(v1.y)) << 16) |
            (unsigned)__bfloat16_as_ushort(__float2bfloat16(v1.x));
    h[3] = ((unsigned)__bfloat16_as_ushort(__float2bfloat16(v1.w)) << 16) |
            (unsigned)__bfloat16_as_ushort(__float2bfloat16(v1.z));
    reinterpret_cast<uint4*>(g_ebf)[row * 8 + sub] =
        make_uint4(h[0], h[1], h[2], h[3]);

    float s = v0.x * v0.x + v0.y * v0.y + v0.z * v0.z + v0.w * v0.w +
              v1.x * v1.x + v1.y * v1.y + v1.z * v1.z + v1.w * v1.w;
    s += __shfl_xor_sync(0xFFFFFFFFu, s, 1);
    s += __shfl_xor_sync(0xFFFFFFFFu, s, 2);
    s += __shfl_xor_sync(0xFFFFFFFFu, s, 4);
    if (sub == 0) { Meta m; m.sq = s; m.tgt = tgt[row]; g_meta[row] = m; }
}

// A tile: 128 rows x 128B (hi). B tile: 64 rows x 128B.
__device__ __forceinline__ void fill_a(uint32_t dst_sb, int row0, int tid) {
    const char* src = reinterpret_cast<const char*>(g_ebf);
#pragma unroll
    for (int k = 0; k < 4; k++) {
        int idx = tid + k * THREADS;          // 128*8 = 1024
        int r = idx >> 3, c8 = idx & 7;
        CP16(dst_sb + r * ROWB + c8 * 16,
             src + (size_t)(row0 + r) * 128 + c8 * 16);
    }
}
__device__ __forceinline__ void fill_b(uint32_t dst_sb, int row0, int tid) {
    const char* src = reinterpret_cast<const char*>(g_ebf);
#pragma unroll
    for (int k = 0; k < 2; k++) {
        int idx = tid + k * THREADS;          // 64*8 = 512
        int r = idx >> 3, c8 = idx & 7;
        CP16(dst_sb + r * ROWB + c8 * 16,
             src + (size_t)(row0 + r) * 128 + c8 * 16);
    }
}

// ---------------------------------------------------------------- kernel 1: mining
__global__ __launch_bounds__(THREADS, 2)
void mine_kernel(const int* __restrict__ tgt) {
    extern __shared__ char smem[];
    const uint32_t sb = smem_u32(smem);
    const int tid = threadIdx.x, wid = tid >> 5, lane = tid & 31;
    const int wm = wid >> 1, wn = wid & 1;       // 4 x 2 warp grid
    const int m_warp = wm * 32, n_warp = wn * 32;
    const int strip = blockIdx.x, split = blockIdx.y;
    const int i0 = strip * BM;
    const int j0 = split * (N_ANCH / JSPLIT);

    // Prologue: G0 = A + B(buf0), G1 = B(buf1)
    fill_a(sb + OFF_A, i0, tid);
    fill_b(sb + OFF_B, j0, tid);
    if (tid < BN)
        reinterpret_cast<Meta*>(smem + OFF_META)[tid] = g_meta[j0 + tid];
    CP_COMMIT();
    fill_b(sb + OFF_B + BSTRIDE, j0 + BN, tid);
    if (tid < BN)
        reinterpret_cast<Meta*>(smem + OFF_META + MSTRIDE)[tid] =
            g_meta[j0 + BN + tid];
    CP_COMMIT();

    int tslot[4];
#pragma unroll
    for (int mt = 0; mt < 2; mt++)
#pragma unroll
        for (int h = 0; h < 2; h++)
            tslot[mt * 2 + h] = tgt[i0 + m_warp + mt * 16 + (lane >> 2) + h * 8];

    const float INF_F = __int_as_float(0x7f800000);
    float mxv[4], mnv[4];
    int   mxj[4], mnj[4];
#pragma unroll
    for (int s = 0; s < 4; s++) {
        mxv[s] = -INF_F; mnv[s] = INF_F; mxj[s] = 0; mnj[s] = 0;
    }

    const uint32_t lmoff = (uint32_t)(lane & 15) * ROWB + ((lane & 16) ? 16 : 0);
    const uint32_t aA = sb + OFF_A + m_warp * ROWB + lmoff;

    // Wait for A + B(0); hoist A fragments (loop-invariant)
    CP_WAIT1();
    __syncthreads();
    uint32_t Af[2][KSTEPS][4];
#pragma unroll
    for (int mt = 0; mt < 2; mt++)
#pragma unroll
        for (int s = 0; s < KSTEPS; s++)
            LDSM_X4(Af[mt][s], aA + mt * (16 * ROWB) + s * 32);

    for (int t = 0; t < CHUNKS; t++) {
        const int buf = t % 3;
        if (t > 0) { CP_WAIT1(); __syncthreads(); }

        const uint32_t aB = sb + OFF_B + buf * BSTRIDE + n_warp * ROWB + lmoff;
        const Meta* meta =
            reinterpret_cast<const Meta*>(smem + OFF_META + buf * MSTRIDE);

        float d[2][4][4];
#pragma unroll
        for (int mt = 0; mt < 2; mt++)
#pragma unroll
            for (int nt = 0; nt < 4; nt++)
#pragma unroll
                for (int e = 0; e < 4; e++) d[mt][nt][e] = 0.f;

#pragma unroll
        for (int s = 0; s < KSTEPS; s++) {
            uint32_t Bf[2][4];
#pragma unroll
            for (int np = 0; np < 2; np++)
                LDSM_X4(Bf[np], aB + np * (16 * ROWB) + s * 32);
#pragma unroll
            for (int mt = 0; mt < 2; mt++)
#pragma unroll
                for (int nt = 0; nt < 4; nt++) {
                    int np = nt >> 1, sel = nt & 1;
                    MMA16816(d[mt][nt], Af[mt][s], Bf[np][sel], Bf[np][2 + sel]);
                }
        }

        // Refill buf (t+2)%3: safe — all warps passed barrier t, so chunk t-1
        // (which used that buffer) is complete block-wide.
        const int jb = j0 + t * BN;
        if (t + 2 < CHUNKS) {
            const int nb = (t + 2) % 3;
            fill_b(sb + OFF_B + nb * BSTRIDE, jb + 2 * BN, tid);
            if (tid < BN)
                reinterpret_cast<Meta*>(smem + OFF_META + nb * MSTRIDE)[tid] =
                    g_meta[jb + 2 * BN + tid];
            CP_COMMIT();
        }

        // Epilogue: predicated conditional updates (8 ops/dot)
#pragma unroll
        for (int nt = 0; nt < 4; nt++)
#pragma unroll
            for (int c = 0; c < 2; c++) {
                int jl = n_warp + nt * 8 + (lane & 3) * 2 + c;
                int j = jb + jl;
                Meta m = meta[jl];
#pragma unroll
                for (int mt = 0; mt < 2; mt++)
#pragma unroll
                    for (int h = 0; h < 2; h++) {
                        int sl = mt * 2 + h;
                        float key = fmaf(-2.0f, d[mt][nt][h * 2 + c], m.sq);
                        bool same = (m.tgt == tslot[sl]);
                        bool cp = same && (key > mxv[sl]);
                        mxv[sl] = cp ? key : mxv[sl];
                        mxj[sl] = cp ? j : mxj[sl];
                        bool cn = (!same) && (key < mnv[sl]);
                        mnv[sl] = cn ? key : mnv[sl];
                        mnj[sl] = cn ? j : mnj[sl];
                    }
            }
    }

    // Reduce across the 4 lanes of each quad (same rows, different j)
#pragma unroll
    for (int s = 0; s < 4; s++) {
#pragma unroll
        for (int off = 1; off <= 2; off <<= 1) {
            float ov = __shfl_xor_sync(0xFFFFFFFFu, mxv[s], off);
            int   oj = __shfl_xor_sync(0xFFFFFFFFu, mxj[s], off);
            if (ov > mxv[s] || (ov == mxv[s] && oj < mxj[s])) {
                mxv[s] = ov; mxj[s] = oj;
            }
            ov = __shfl_xor_sync(0xFFFFFFFFu, mnv[s], off);
            oj = __shfl_xor_sync(0xFFFFFFFFu, mnj[s], off);
            if (ov < mnv[s] || (ov == mnv[s] && oj < mnj[s])) {
                mnv[s] = ov; mnj[s] = oj;
            }
        }
    }

    // Cross-warp combine through smem (overlay on B region)
    float* s_mv = reinterpret_cast<float*>(smem + OFF_B);
    int*   s_mj = reinterpret_cast<int*>(smem + OFF_B + 1024);
    float* s_nv = reinterpret_cast<float*>(smem + OFF_B + 2048);
    int*   s_nj = reinterpret_cast<int*>(smem + OFF_B + 3072);
    __syncthreads();
    if ((lane & 3) == 0) {
#pragma unroll
        for (int mt = 0; mt < 2; mt++)
#pragma unroll
            for (int h = 0; h < 2; h++) {
                int sl = mt * 2 + h;
                int row = m_warp + mt * 16 + (lane >> 2) + h * 8;
                int o = wn * 128 + row;
                s_mv[o] = mxv[sl]; s_mj[o] = mxj[sl];
                s_nv[o] = mnv[sl]; s_nj[o] = mnj[sl];
            }
    }
    __syncthreads();
    if (tid < 128) {
        float bv = -INF_F, sv = INF_F;
        int bj = 0, sj = 0;
#pragma unroll
        for (int w = 0; w < 2; w++) {
            int o = w * 128 + tid;
            float v = s_mv[o]; int j = s_mj[o];
            if (v > bv || (v == bv && j < bj)) { bv = v; bj = j; }
            v = s_nv[o]; j = s_nj[o];
            if (v < sv || (v == sv && j < sj)) { sv = v; sj = j; }
        }
        const int oi = split * N_ANCH + i0 + tid;
        g_maxval[oi] = bv; g_maxidx[oi] = bj;
        g_minval[oi] = sv; g_minidx[oi] = sj;
    }
}

// ---------------------------------------------------------------- kernel 2: loss + mean
__global__ void loss_kernel(const float* __restrict__ emb,
                            float* __restrict__ out) {
    __shared__ float red[64];
    const int tid = threadIdx.x;
    const int i = blockIdx.x * 64 + (tid >> 2);
    const int sub = tid & 3;

    const float INF_F = __int_as_float(0x7f800000);
    float maxv = -INF_F; int p = 0;
    float minv =  INF_F; int n = 0;
#pragma unroll
    for (int s = 0; s < JSPLIT; s++) {
        const int o = s * N_ANCH + i;
        float v = g_maxval[o];
        if (v > maxv) { maxv = v; p = g_maxidx[o]; }
        v = g_minval[o];
        if (v < minv) { minv = v; n = g_minidx[o]; }
    }

    const float4* ei = reinterpret_cast<const float4*>(emb + (size_t)i * DIM) + sub * 4;
    const float4* ep = reinterpret_cast<const float4*>(emb + (size_t)p * DIM) + sub * 4;
    const float4* en = reinterpret_cast<const float4*>(emb + (size_t)n * DIM) + sub * 4;
    float ap = 0.f, an = 0.f;
#pragma unroll
    for (int k = 0; k < 4; k++) {
        float4 vi = ei[k], vp = ep[k], vn = en[k];
        float dx;
        dx = vi.x - vp.x; ap += dx * dx;
        dx = vi.y - vp.y; ap += dx * dx;
        dx = vi.z - vp.z; ap += dx * dx;
        dx = vi.w - vp.w; ap += dx * dx;
        dx = vi.x - vn.x; an += dx * dx;
        dx = vi.y - vn.y; an += dx * dx;
        dx = vi.z - vn.z; an += dx * dx;
        dx = vi.w - vn.w; an += dx * dx;
    }
    float v = ap - an;
    v += __shfl_xor_sync(0xFFFFFFFFu, v, 1);
    v += __shfl_xor_sync(0xFFFFFFFFu, v, 2);
    if (sub == 0) red[tid >> 2] = fmaxf(v + MARGIN_F, 0.0f);
    __syncthreads();

#pragma unroll
    for (int off = 32; off > 0; off >>= 1) {
        if (tid < off) red[tid] += red[tid + off];
        __syncthreads();
    }
    if (tid == 0) {
        g_partial[blockIdx.x] = red[0];
        __threadfence();
        unsigned int ticket = atomicAdd(&g_count, 1u);
        if (ticket == RBLOCKS - 1) {            // last block: fixed-order sum
            float s = 0.f;
#pragma unroll
            for (int k = 0; k < RBLOCKS; k++) s += g_partial[k];
            out[0] = s / (float)N_ANCH;
        }
    }
}

// ----------------------------------------------------------------
extern "C" void kernel_launch(void* const* d_in, const int* in_sizes, int n_in,
                              void* d_out, int out_size) {
    const float* emb = (const float*)d_in[0];
    const int*   tgt = (const int*)d_in[1];
    float*       out = (float*)d_out;

    cudaFuncSetAttribute(mine_kernel, cudaFuncAttributeMaxDynamicSharedMemorySize,
                         SMEM_TOTAL);

    prep_kernel<<<(N_ANCH * 8) / 256, 256>>>(emb, tgt);
    dim3 grid(STRIPS, JSPLIT);
    mine_kernel<<<grid, THREADS, SMEM_TOTAL>>>(tgt);
    loss_kernel<<<RBLOCKS, 256>>>(emb, out);
}